// round 8
// baseline (speedup 1.0000x reference)
#include <cuda_runtime.h>
#include <cstdint>

#define Tn 4096
#define Hn 1024
#define Dn 2048
#define En 8
#define Kn 2
#define NP (Tn*Kn)   // 8192 token-expert pairs (upper bound)

#define BM 64
#define BN 64
#define BK 16

// ---------------- scratch (device globals; no cudaMalloc allowed) ----------
__device__ int   g_cnt[En];
__device__ int   g_off[En + 1];
__device__ int   g_cur[En];
__device__ int   g_tok[NP];
__device__ float g_w[NP];
__device__ __align__(16) float g_act[(size_t)NP * Dn];   // 64 MiB intermediate

// ---------------- routing -------------------------------------------------
__global__ void k_reset(float* __restrict__ out) {
    int i = blockIdx.x * blockDim.x + threadIdx.x;
    if (i < Tn * Hn) out[i] = 0.f;
    if (i < En) { g_cnt[i] = 0; g_cur[i] = 0; }
}

// Reference scatter is .set (last-wins): if the two ids of a token are equal,
// only the k=1 entry (weight w1) contributes.
__global__ void k_count(const int* __restrict__ ids) {
    int p = blockIdx.x * blockDim.x + threadIdx.x;
    if (p >= NP) return;
    int t = p >> 1, k = p & 1;
    bool valid = (k == 1) || (ids[2 * t] != ids[2 * t + 1]);
    if (valid) atomicAdd(&g_cnt[ids[p]], 1);
}

__global__ void k_scan() {
    int s = 0;
    g_off[0] = 0;
    for (int e = 0; e < En; e++) { s += g_cnt[e]; g_off[e + 1] = s; }
}

__global__ void k_place(const int* __restrict__ ids, const float* __restrict__ w) {
    int p = blockIdx.x * blockDim.x + threadIdx.x;
    if (p >= NP) return;
    int t = p >> 1, k = p & 1;
    bool valid = (k == 1) || (ids[2 * t] != ids[2 * t + 1]);
    if (!valid) return;
    int e = ids[p];
    int pos = g_off[e] + atomicAdd(&g_cur[e], 1);
    g_tok[pos] = t;
    g_w[pos]   = w[p];
}

// ---------------- GEMM1: act = silu(Xg @ wi_0[e]) * (Xg @ wi_1[e]) ---------
// Tile 64x64x16, 256 threads, 4x4 microtile per thread, two accumulators
// (gate + up) sharing one A tile.
__global__ __launch_bounds__(256) void k_gemm1(
    const float* __restrict__ X,
    const float* __restrict__ W0,
    const float* __restrict__ W1)
{
    __shared__ float As[BK][BM + 4];      // +4 keeps float4 alignment, kills conflicts
    __shared__ float B0s[BK][BN];
    __shared__ float B1s[BK][BN];
    __shared__ int   toks[BM];

    int e   = blockIdx.z;
    int beg = g_off[e];
    int ne  = g_off[e + 1] - beg;
    int r0  = blockIdx.y * BM;
    if (r0 >= ne) return;                 // uniform early-exit for empty tiles
    int n0  = blockIdx.x * BN;

    int tid = threadIdx.x;
    int tx  = tid & 15, ty = tid >> 4;

    if (tid < BM) {
        int r = r0 + tid;
        toks[tid] = (r < ne) ? g_tok[beg + r] : -1;
    }
    __syncthreads();

    const float* w0e = W0 + (size_t)e * Hn * Dn;
    const float* w1e = W1 + (size_t)e * Hn * Dn;

    // A-load mapping: each thread loads float4 along k of one gathered row
    int am = (tid * 4) >> 4;              // 0..63
    int ak = (tid * 4) & 15;              // 0,4,8,12
    int atok = toks[am];
    const float* aptr = (atok >= 0) ? (X + (size_t)atok * Hn + ak) : nullptr;
    // B-load mapping: float4 along n, coalesced
    int bn = (tid * 4) & 63;
    int bk = (tid * 4) >> 6;

    float acc0[4][4] = {}, acc1[4][4] = {};

    for (int k0 = 0; k0 < Hn; k0 += BK) {
        float4 av = make_float4(0.f, 0.f, 0.f, 0.f);
        if (aptr) av = *reinterpret_cast<const float4*>(aptr + k0);
        As[ak + 0][am] = av.x; As[ak + 1][am] = av.y;
        As[ak + 2][am] = av.z; As[ak + 3][am] = av.w;

        *reinterpret_cast<float4*>(&B0s[bk][bn]) =
            *reinterpret_cast<const float4*>(w0e + (size_t)(k0 + bk) * Dn + n0 + bn);
        *reinterpret_cast<float4*>(&B1s[bk][bn]) =
            *reinterpret_cast<const float4*>(w1e + (size_t)(k0 + bk) * Dn + n0 + bn);
        __syncthreads();

        #pragma unroll
        for (int kk = 0; kk < BK; kk++) {
            float4 a  = *reinterpret_cast<const float4*>(&As[kk][ty * 4]);
            float4 b0 = *reinterpret_cast<const float4*>(&B0s[kk][tx * 4]);
            float4 b1 = *reinterpret_cast<const float4*>(&B1s[kk][tx * 4]);
            float aa[4]  = {a.x, a.y, a.z, a.w};
            float bb0[4] = {b0.x, b0.y, b0.z, b0.w};
            float bb1[4] = {b1.x, b1.y, b1.z, b1.w};
            #pragma unroll
            for (int i = 0; i < 4; i++)
                #pragma unroll
                for (int j = 0; j < 4; j++) {
                    acc0[i][j] += aa[i] * bb0[j];
                    acc1[i][j] += aa[i] * bb1[j];
                }
        }
        __syncthreads();
    }

    #pragma unroll
    for (int i = 0; i < 4; i++) {
        int r = r0 + ty * 4 + i;
        if (r >= ne) continue;
        float4 o;
        float v[4];
        #pragma unroll
        for (int j = 0; j < 4; j++) {
            float g = acc0[i][j];
            float s = g / (1.f + __expf(-g));   // silu
            v[j] = s * acc1[i][j];
        }
        o.x = v[0]; o.y = v[1]; o.z = v[2]; o.w = v[3];
        *reinterpret_cast<float4*>(&g_act[(size_t)(beg + r) * Dn + n0 + tx * 4]) = o;
    }
}

// ---------------- GEMM2: out[tok] += w * (act @ wo[e]) ---------------------
__global__ __launch_bounds__(256) void k_gemm2(
    const float* __restrict__ WO,
    float* __restrict__ out)
{
    __shared__ float As[BK][BM + 4];
    __shared__ float Bs[BK][BN];
    __shared__ int   toks[BM];
    __shared__ float ws[BM];

    int e   = blockIdx.z;
    int beg = g_off[e];
    int ne  = g_off[e + 1] - beg;
    int r0  = blockIdx.y * BM;
    if (r0 >= ne) return;
    int n0  = blockIdx.x * BN;

    int tid = threadIdx.x;
    int tx  = tid & 15, ty = tid >> 4;

    if (tid < BM) {
        int r = r0 + tid;
        if (r < ne) { toks[tid] = g_tok[beg + r]; ws[tid] = g_w[beg + r]; }
        else        { toks[tid] = -1;             ws[tid] = 0.f; }
    }
    __syncthreads();

    const float* we = WO + (size_t)e * Dn * Hn;

    int am = (tid * 4) >> 4;
    int ak = (tid * 4) & 15;
    int arow = r0 + am;
    const float* aptr = (arow < ne) ? &g_act[(size_t)(beg + arow) * Dn + ak] : nullptr;
    int bn = (tid * 4) & 63;
    int bk = (tid * 4) >> 6;

    float acc[4][4] = {};

    for (int k0 = 0; k0 < Dn; k0 += BK) {
        float4 av = make_float4(0.f, 0.f, 0.f, 0.f);
        if (aptr) av = *reinterpret_cast<const float4*>(aptr + k0);
        As[ak + 0][am] = av.x; As[ak + 1][am] = av.y;
        As[ak + 2][am] = av.z; As[ak + 3][am] = av.w;

        *reinterpret_cast<float4*>(&Bs[bk][bn]) =
            *reinterpret_cast<const float4*>(we + (size_t)(k0 + bk) * Hn + n0 + bn);
        __syncthreads();

        #pragma unroll
        for (int kk = 0; kk < BK; kk++) {
            float4 a = *reinterpret_cast<const float4*>(&As[kk][ty * 4]);
            float4 b = *reinterpret_cast<const float4*>(&Bs[kk][tx * 4]);
            float aa[4] = {a.x, a.y, a.z, a.w};
            float bb[4] = {b.x, b.y, b.z, b.w};
            #pragma unroll
            for (int i = 0; i < 4; i++)
                #pragma unroll
                for (int j = 0; j < 4; j++)
                    acc[i][j] += aa[i] * bb[j];
        }
        __syncthreads();
    }

    #pragma unroll
    for (int i = 0; i < 4; i++) {
        int r = r0 + ty * 4 + i;
        if (r >= ne) continue;
        int   tok = toks[ty * 4 + i];
        float wgt = ws[ty * 4 + i];
        float* op = out + (size_t)tok * Hn + n0 + tx * 4;
        #pragma unroll
        for (int j = 0; j < 4; j++)
            atomicAdd(op + j, wgt * acc[i][j]);
    }
}

// ---------------- launch ----------------------------------------------------
extern "C" void kernel_launch(void* const* d_in, const int* in_sizes, int n_in,
                              void* d_out, int out_size) {
    const float* X  = (const float*)d_in[0];   // hidden_states [T,H]
    const float* tw = (const float*)d_in[1];   // topk_weights  [T,K]
    const int*   ti = (const int*)d_in[2];     // topk_ids      [T,K]
    const float* W0 = (const float*)d_in[3];   // wi_0 [E,H,D]
    const float* W1 = (const float*)d_in[4];   // wi_1 [E,H,D]
    const float* WO = (const float*)d_in[5];   // wo   [E,D,H]
    float* out = (float*)d_out;                // [T,H] f32

    k_reset<<<(Tn * Hn + 255) / 256, 256>>>(out);
    k_count<<<(NP + 255) / 256, 256>>>(ti);
    k_scan<<<1, 1>>>();
    k_place<<<(NP + 255) / 256, 256>>>(ti, tw);

    dim3 g1(Dn / BN, NP / BM, En);   // (32, 128, 8); empty row-tiles exit early
    k_gemm1<<<g1, 256>>>(X, W0, W1);

    dim3 g2(Hn / BN, NP / BM, En);   // (16, 128, 8)
    k_gemm2<<<g2, 256>>>(WO, out);
}

// round 9
// speedup vs baseline: 1.0016x; 1.0016x over previous
#include <cuda_runtime.h>
#include <cstdint>

#define Tn 4096
#define Hn 1024
#define Dn 2048
#define En 8
#define Kn 2
#define NP (Tn*Kn)   // 8192 token-expert pairs (upper bound)

#define BM 64
#define BN 64
#define BK 16

// ---------------- scratch (device globals; no cudaMalloc allowed) ----------
__device__ int   g_cnt[En];
__device__ int   g_off[En + 1];
__device__ int   g_cur[En];
__device__ int   g_tok[NP];
__device__ float g_w[NP];
__device__ __align__(16) float g_act[(size_t)NP * Dn];   // 64 MiB intermediate

// ---------------- routing -------------------------------------------------
__global__ void k_reset(float* __restrict__ out) {
    int i = blockIdx.x * blockDim.x + threadIdx.x;
    if (i < Tn * Hn) out[i] = 0.f;
    if (i < En) { g_cnt[i] = 0; g_cur[i] = 0; }
}

// Reference scatter is .set (last-wins): if the two ids of a token are equal,
// only the k=1 entry (weight w1) contributes.
__global__ void k_count(const int* __restrict__ ids) {
    int p = blockIdx.x * blockDim.x + threadIdx.x;
    if (p >= NP) return;
    int t = p >> 1, k = p & 1;
    bool valid = (k == 1) || (ids[2 * t] != ids[2 * t + 1]);
    if (valid) atomicAdd(&g_cnt[ids[p]], 1);
}

__global__ void k_scan() {
    int s = 0;
    g_off[0] = 0;
    for (int e = 0; e < En; e++) { s += g_cnt[e]; g_off[e + 1] = s; }
}

__global__ void k_place(const int* __restrict__ ids, const float* __restrict__ w) {
    int p = blockIdx.x * blockDim.x + threadIdx.x;
    if (p >= NP) return;
    int t = p >> 1, k = p & 1;
    bool valid = (k == 1) || (ids[2 * t] != ids[2 * t + 1]);
    if (!valid) return;
    int e = ids[p];
    int pos = g_off[e] + atomicAdd(&g_cur[e], 1);
    g_tok[pos] = t;
    g_w[pos]   = w[p];
}

// ---------------- GEMM1: act = silu(Xg @ wi_0[e]) * (Xg @ wi_1[e]) ---------
// Tile 64x64x16, 256 threads, 4x4 microtile per thread, two accumulators
// (gate + up) sharing one A tile.
__global__ __launch_bounds__(256) void k_gemm1(
    const float* __restrict__ X,
    const float* __restrict__ W0,
    const float* __restrict__ W1)
{
    __shared__ float As[BK][BM + 4];      // +4 keeps float4 alignment, kills conflicts
    __shared__ float B0s[BK][BN];
    __shared__ float B1s[BK][BN];
    __shared__ int   toks[BM];

    int e   = blockIdx.z;
    int beg = g_off[e];
    int ne  = g_off[e + 1] - beg;
    int r0  = blockIdx.y * BM;
    if (r0 >= ne) return;                 // uniform early-exit for empty tiles
    int n0  = blockIdx.x * BN;

    int tid = threadIdx.x;
    int tx  = tid & 15, ty = tid >> 4;

    if (tid < BM) {
        int r = r0 + tid;
        toks[tid] = (r < ne) ? g_tok[beg + r] : -1;
    }
    __syncthreads();

    const float* w0e = W0 + (size_t)e * Hn * Dn;
    const float* w1e = W1 + (size_t)e * Hn * Dn;

    // A-load mapping: each thread loads float4 along k of one gathered row
    int am = (tid * 4) >> 4;              // 0..63
    int ak = (tid * 4) & 15;              // 0,4,8,12
    int atok = toks[am];
    const float* aptr = (atok >= 0) ? (X + (size_t)atok * Hn + ak) : nullptr;
    // B-load mapping: float4 along n, coalesced
    int bn = (tid * 4) & 63;
    int bk = (tid * 4) >> 6;

    float acc0[4][4] = {}, acc1[4][4] = {};

    for (int k0 = 0; k0 < Hn; k0 += BK) {
        float4 av = make_float4(0.f, 0.f, 0.f, 0.f);
        if (aptr) av = *reinterpret_cast<const float4*>(aptr + k0);
        As[ak + 0][am] = av.x; As[ak + 1][am] = av.y;
        As[ak + 2][am] = av.z; As[ak + 3][am] = av.w;

        *reinterpret_cast<float4*>(&B0s[bk][bn]) =
            *reinterpret_cast<const float4*>(w0e + (size_t)(k0 + bk) * Dn + n0 + bn);
        *reinterpret_cast<float4*>(&B1s[bk][bn]) =
            *reinterpret_cast<const float4*>(w1e + (size_t)(k0 + bk) * Dn + n0 + bn);
        __syncthreads();

        #pragma unroll
        for (int kk = 0; kk < BK; kk++) {
            float4 a  = *reinterpret_cast<const float4*>(&As[kk][ty * 4]);
            float4 b0 = *reinterpret_cast<const float4*>(&B0s[kk][tx * 4]);
            float4 b1 = *reinterpret_cast<const float4*>(&B1s[kk][tx * 4]);
            float aa[4]  = {a.x, a.y, a.z, a.w};
            float bb0[4] = {b0.x, b0.y, b0.z, b0.w};
            float bb1[4] = {b1.x, b1.y, b1.z, b1.w};
            #pragma unroll
            for (int i = 0; i < 4; i++)
                #pragma unroll
                for (int j = 0; j < 4; j++) {
                    acc0[i][j] += aa[i] * bb0[j];
                    acc1[i][j] += aa[i] * bb1[j];
                }
        }
        __syncthreads();
    }

    #pragma unroll
    for (int i = 0; i < 4; i++) {
        int r = r0 + ty * 4 + i;
        if (r >= ne) continue;
        float4 o;
        float v[4];
        #pragma unroll
        for (int j = 0; j < 4; j++) {
            float g = acc0[i][j];
            float s = g / (1.f + __expf(-g));   // silu
            v[j] = s * acc1[i][j];
        }
        o.x = v[0]; o.y = v[1]; o.z = v[2]; o.w = v[3];
        *reinterpret_cast<float4*>(&g_act[(size_t)(beg + r) * Dn + n0 + tx * 4]) = o;
    }
}

// ---------------- GEMM2: out[tok] += w * (act @ wo[e]) ---------------------
__global__ __launch_bounds__(256) void k_gemm2(
    const float* __restrict__ WO,
    float* __restrict__ out)
{
    __shared__ float As[BK][BM + 4];
    __shared__ float Bs[BK][BN];
    __shared__ int   toks[BM];
    __shared__ float ws[BM];

    int e   = blockIdx.z;
    int beg = g_off[e];
    int ne  = g_off[e + 1] - beg;
    int r0  = blockIdx.y * BM;
    if (r0 >= ne) return;
    int n0  = blockIdx.x * BN;

    int tid = threadIdx.x;
    int tx  = tid & 15, ty = tid >> 4;

    if (tid < BM) {
        int r = r0 + tid;
        if (r < ne) { toks[tid] = g_tok[beg + r]; ws[tid] = g_w[beg + r]; }
        else        { toks[tid] = -1;             ws[tid] = 0.f; }
    }
    __syncthreads();

    const float* we = WO + (size_t)e * Dn * Hn;

    int am = (tid * 4) >> 4;
    int ak = (tid * 4) & 15;
    int arow = r0 + am;
    const float* aptr = (arow < ne) ? &g_act[(size_t)(beg + arow) * Dn + ak] : nullptr;
    int bn = (tid * 4) & 63;
    int bk = (tid * 4) >> 6;

    float acc[4][4] = {};

    for (int k0 = 0; k0 < Dn; k0 += BK) {
        float4 av = make_float4(0.f, 0.f, 0.f, 0.f);
        if (aptr) av = *reinterpret_cast<const float4*>(aptr + k0);
        As[ak + 0][am] = av.x; As[ak + 1][am] = av.y;
        As[ak + 2][am] = av.z; As[ak + 3][am] = av.w;

        *reinterpret_cast<float4*>(&Bs[bk][bn]) =
            *reinterpret_cast<const float4*>(we + (size_t)(k0 + bk) * Hn + n0 + bn);
        __syncthreads();

        #pragma unroll
        for (int kk = 0; kk < BK; kk++) {
            float4 a = *reinterpret_cast<const float4*>(&As[kk][ty * 4]);
            float4 b = *reinterpret_cast<const float4*>(&Bs[kk][tx * 4]);
            float aa[4] = {a.x, a.y, a.z, a.w};
            float bb[4] = {b.x, b.y, b.z, b.w};
            #pragma unroll
            for (int i = 0; i < 4; i++)
                #pragma unroll
                for (int j = 0; j < 4; j++)
                    acc[i][j] += aa[i] * bb[j];
        }
        __syncthreads();
    }

    #pragma unroll
    for (int i = 0; i < 4; i++) {
        int r = r0 + ty * 4 + i;
        if (r >= ne) continue;
        int   tok = toks[ty * 4 + i];
        float wgt = ws[ty * 4 + i];
        float* op = out + (size_t)tok * Hn + n0 + tx * 4;
        #pragma unroll
        for (int j = 0; j < 4; j++)
            atomicAdd(op + j, wgt * acc[i][j]);
    }
}

// ---------------- launch ----------------------------------------------------
extern "C" void kernel_launch(void* const* d_in, const int* in_sizes, int n_in,
                              void* d_out, int out_size) {
    const float* X  = (const float*)d_in[0];   // hidden_states [T,H]
    const float* tw = (const float*)d_in[1];   // topk_weights  [T,K]
    const int*   ti = (const int*)d_in[2];     // topk_ids      [T,K]
    const float* W0 = (const float*)d_in[3];   // wi_0 [E,H,D]
    const float* W1 = (const float*)d_in[4];   // wi_1 [E,H,D]
    const float* WO = (const float*)d_in[5];   // wo   [E,D,H]
    float* out = (float*)d_out;                // [T,H] f32

    k_reset<<<(Tn * Hn + 255) / 256, 256>>>(out);
    k_count<<<(NP + 255) / 256, 256>>>(ti);
    k_scan<<<1, 1>>>();
    k_place<<<(NP + 255) / 256, 256>>>(ti, tw);

    dim3 g1(Dn / BN, NP / BM, En);   // (32, 128, 8); empty row-tiles exit early
    k_gemm1<<<g1, 256>>>(X, W0, W1);

    dim3 g2(Hn / BN, NP / BM, En);   // (16, 128, 8)
    k_gemm2<<<g2, 256>>>(WO, out);
}

// round 10
// speedup vs baseline: 1.0050x; 1.0034x over previous
#include <cuda_runtime.h>
#include <cstdint>

#define Tn 4096
#define Hn 1024
#define Dn 2048
#define En 8
#define Kn 2
#define NP (Tn*Kn)   // 8192 token-expert pairs (upper bound)

#define BM 64
#define BN 64
#define BK 16

// ---------------- scratch (device globals; no cudaMalloc allowed) ----------
__device__ int   g_cnt[En];
__device__ int   g_off[En + 1];
__device__ int   g_cur[En];
__device__ int   g_tok[NP];
__device__ float g_w[NP];
__device__ __align__(16) float g_act[(size_t)NP * Dn];   // 64 MiB intermediate

// ---------------- routing -------------------------------------------------
__global__ void k_reset(float* __restrict__ out) {
    int i = blockIdx.x * blockDim.x + threadIdx.x;
    if (i < Tn * Hn) out[i] = 0.f;
    if (i < En) { g_cnt[i] = 0; g_cur[i] = 0; }
}

// Reference scatter is .set (last-wins): if the two ids of a token are equal,
// only the k=1 entry (weight w1) contributes.
__global__ void k_count(const int* __restrict__ ids) {
    int p = blockIdx.x * blockDim.x + threadIdx.x;
    if (p >= NP) return;
    int t = p >> 1, k = p & 1;
    bool valid = (k == 1) || (ids[2 * t] != ids[2 * t + 1]);
    if (valid) atomicAdd(&g_cnt[ids[p]], 1);
}

__global__ void k_scan() {
    int s = 0;
    g_off[0] = 0;
    for (int e = 0; e < En; e++) { s += g_cnt[e]; g_off[e + 1] = s; }
}

__global__ void k_place(const int* __restrict__ ids, const float* __restrict__ w) {
    int p = blockIdx.x * blockDim.x + threadIdx.x;
    if (p >= NP) return;
    int t = p >> 1, k = p & 1;
    bool valid = (k == 1) || (ids[2 * t] != ids[2 * t + 1]);
    if (!valid) return;
    int e = ids[p];
    int pos = g_off[e] + atomicAdd(&g_cur[e], 1);
    g_tok[pos] = t;
    g_w[pos]   = w[p];
}

// ---------------- GEMM1: act = silu(Xg @ wi_0[e]) * (Xg @ wi_1[e]) ---------
// Tile 64x64x16, 256 threads, 4x4 microtile per thread, two accumulators
// (gate + up) sharing one A tile.
__global__ __launch_bounds__(256) void k_gemm1(
    const float* __restrict__ X,
    const float* __restrict__ W0,
    const float* __restrict__ W1)
{
    __shared__ float As[BK][BM + 4];      // +4 keeps float4 alignment, kills conflicts
    __shared__ float B0s[BK][BN];
    __shared__ float B1s[BK][BN];
    __shared__ int   toks[BM];

    int e   = blockIdx.z;
    int beg = g_off[e];
    int ne  = g_off[e + 1] - beg;
    int r0  = blockIdx.y * BM;
    if (r0 >= ne) return;                 // uniform early-exit for empty tiles
    int n0  = blockIdx.x * BN;

    int tid = threadIdx.x;
    int tx  = tid & 15, ty = tid >> 4;

    if (tid < BM) {
        int r = r0 + tid;
        toks[tid] = (r < ne) ? g_tok[beg + r] : -1;
    }
    __syncthreads();

    const float* w0e = W0 + (size_t)e * Hn * Dn;
    const float* w1e = W1 + (size_t)e * Hn * Dn;

    // A-load mapping: each thread loads float4 along k of one gathered row
    int am = (tid * 4) >> 4;              // 0..63
    int ak = (tid * 4) & 15;              // 0,4,8,12
    int atok = toks[am];
    const float* aptr = (atok >= 0) ? (X + (size_t)atok * Hn + ak) : nullptr;
    // B-load mapping: float4 along n, coalesced
    int bn = (tid * 4) & 63;
    int bk = (tid * 4) >> 6;

    float acc0[4][4] = {}, acc1[4][4] = {};

    for (int k0 = 0; k0 < Hn; k0 += BK) {
        float4 av = make_float4(0.f, 0.f, 0.f, 0.f);
        if (aptr) av = *reinterpret_cast<const float4*>(aptr + k0);
        As[ak + 0][am] = av.x; As[ak + 1][am] = av.y;
        As[ak + 2][am] = av.z; As[ak + 3][am] = av.w;

        *reinterpret_cast<float4*>(&B0s[bk][bn]) =
            *reinterpret_cast<const float4*>(w0e + (size_t)(k0 + bk) * Dn + n0 + bn);
        *reinterpret_cast<float4*>(&B1s[bk][bn]) =
            *reinterpret_cast<const float4*>(w1e + (size_t)(k0 + bk) * Dn + n0 + bn);
        __syncthreads();

        #pragma unroll
        for (int kk = 0; kk < BK; kk++) {
            float4 a  = *reinterpret_cast<const float4*>(&As[kk][ty * 4]);
            float4 b0 = *reinterpret_cast<const float4*>(&B0s[kk][tx * 4]);
            float4 b1 = *reinterpret_cast<const float4*>(&B1s[kk][tx * 4]);
            float aa[4]  = {a.x, a.y, a.z, a.w};
            float bb0[4] = {b0.x, b0.y, b0.z, b0.w};
            float bb1[4] = {b1.x, b1.y, b1.z, b1.w};
            #pragma unroll
            for (int i = 0; i < 4; i++)
                #pragma unroll
                for (int j = 0; j < 4; j++) {
                    acc0[i][j] += aa[i] * bb0[j];
                    acc1[i][j] += aa[i] * bb1[j];
                }
        }
        __syncthreads();
    }

    #pragma unroll
    for (int i = 0; i < 4; i++) {
        int r = r0 + ty * 4 + i;
        if (r >= ne) continue;
        float4 o;
        float v[4];
        #pragma unroll
        for (int j = 0; j < 4; j++) {
            float g = acc0[i][j];
            float s = g / (1.f + __expf(-g));   // silu
            v[j] = s * acc1[i][j];
        }
        o.x = v[0]; o.y = v[1]; o.z = v[2]; o.w = v[3];
        *reinterpret_cast<float4*>(&g_act[(size_t)(beg + r) * Dn + n0 + tx * 4]) = o;
    }
}

// ---------------- GEMM2: out[tok] += w * (act @ wo[e]) ---------------------
__global__ __launch_bounds__(256) void k_gemm2(
    const float* __restrict__ WO,
    float* __restrict__ out)
{
    __shared__ float As[BK][BM + 4];
    __shared__ float Bs[BK][BN];
    __shared__ int   toks[BM];
    __shared__ float ws[BM];

    int e   = blockIdx.z;
    int beg = g_off[e];
    int ne  = g_off[e + 1] - beg;
    int r0  = blockIdx.y * BM;
    if (r0 >= ne) return;
    int n0  = blockIdx.x * BN;

    int tid = threadIdx.x;
    int tx  = tid & 15, ty = tid >> 4;

    if (tid < BM) {
        int r = r0 + tid;
        if (r < ne) { toks[tid] = g_tok[beg + r]; ws[tid] = g_w[beg + r]; }
        else        { toks[tid] = -1;             ws[tid] = 0.f; }
    }
    __syncthreads();

    const float* we = WO + (size_t)e * Dn * Hn;

    int am = (tid * 4) >> 4;
    int ak = (tid * 4) & 15;
    int arow = r0 + am;
    const float* aptr = (arow < ne) ? &g_act[(size_t)(beg + arow) * Dn + ak] : nullptr;
    int bn = (tid * 4) & 63;
    int bk = (tid * 4) >> 6;

    float acc[4][4] = {};

    for (int k0 = 0; k0 < Dn; k0 += BK) {
        float4 av = make_float4(0.f, 0.f, 0.f, 0.f);
        if (aptr) av = *reinterpret_cast<const float4*>(aptr + k0);
        As[ak + 0][am] = av.x; As[ak + 1][am] = av.y;
        As[ak + 2][am] = av.z; As[ak + 3][am] = av.w;

        *reinterpret_cast<float4*>(&Bs[bk][bn]) =
            *reinterpret_cast<const float4*>(we + (size_t)(k0 + bk) * Hn + n0 + bn);
        __syncthreads();

        #pragma unroll
        for (int kk = 0; kk < BK; kk++) {
            float4 a = *reinterpret_cast<const float4*>(&As[kk][ty * 4]);
            float4 b = *reinterpret_cast<const float4*>(&Bs[kk][tx * 4]);
            float aa[4] = {a.x, a.y, a.z, a.w};
            float bb[4] = {b.x, b.y, b.z, b.w};
            #pragma unroll
            for (int i = 0; i < 4; i++)
                #pragma unroll
                for (int j = 0; j < 4; j++)
                    acc[i][j] += aa[i] * bb[j];
        }
        __syncthreads();
    }

    #pragma unroll
    for (int i = 0; i < 4; i++) {
        int r = r0 + ty * 4 + i;
        if (r >= ne) continue;
        int   tok = toks[ty * 4 + i];
        float wgt = ws[ty * 4 + i];
        float* op = out + (size_t)tok * Hn + n0 + tx * 4;
        #pragma unroll
        for (int j = 0; j < 4; j++)
            atomicAdd(op + j, wgt * acc[i][j]);
    }
}

// ---------------- launch ----------------------------------------------------
extern "C" void kernel_launch(void* const* d_in, const int* in_sizes, int n_in,
                              void* d_out, int out_size) {
    const float* X  = (const float*)d_in[0];   // hidden_states [T,H]
    const float* tw = (const float*)d_in[1];   // topk_weights  [T,K]
    const int*   ti = (const int*)d_in[2];     // topk_ids      [T,K]
    const float* W0 = (const float*)d_in[3];   // wi_0 [E,H,D]
    const float* W1 = (const float*)d_in[4];   // wi_1 [E,H,D]
    const float* WO = (const float*)d_in[5];   // wo   [E,D,H]
    float* out = (float*)d_out;                // [T,H] f32

    k_reset<<<(Tn * Hn + 255) / 256, 256>>>(out);
    k_count<<<(NP + 255) / 256, 256>>>(ti);
    k_scan<<<1, 1>>>();
    k_place<<<(NP + 255) / 256, 256>>>(ti, tw);

    dim3 g1(Dn / BN, NP / BM, En);   // (32, 128, 8); empty row-tiles exit early
    k_gemm1<<<g1, 256>>>(X, W0, W1);

    dim3 g2(Hn / BN, NP / BM, En);   // (16, 128, 8)
    k_gemm2<<<g2, 256>>>(WO, out);
}

// round 11
// speedup vs baseline: 1.0055x; 1.0005x over previous
#include <cuda_runtime.h>
#include <cstdint>

#define Tn 4096
#define Hn 1024
#define Dn 2048
#define En 8
#define Kn 2
#define NP (Tn*Kn)   // 8192 token-expert pairs (upper bound)

#define BM 64
#define BN 64
#define BK 16

// ---------------- scratch (device globals; no cudaMalloc allowed) ----------
__device__ int   g_cnt[En];
__device__ int   g_off[En + 1];
__device__ int   g_cur[En];
__device__ int   g_tok[NP];
__device__ float g_w[NP];
__device__ __align__(16) float g_act[(size_t)NP * Dn];   // 64 MiB intermediate

// ---------------- routing -------------------------------------------------
__global__ void k_reset(float* __restrict__ out) {
    int i = blockIdx.x * blockDim.x + threadIdx.x;
    if (i < Tn * Hn) out[i] = 0.f;
    if (i < En) { g_cnt[i] = 0; g_cur[i] = 0; }
}

// Reference scatter is .set (last-wins): if the two ids of a token are equal,
// only the k=1 entry (weight w1) contributes.
__global__ void k_count(const int* __restrict__ ids) {
    int p = blockIdx.x * blockDim.x + threadIdx.x;
    if (p >= NP) return;
    int t = p >> 1, k = p & 1;
    bool valid = (k == 1) || (ids[2 * t] != ids[2 * t + 1]);
    if (valid) atomicAdd(&g_cnt[ids[p]], 1);
}

__global__ void k_scan() {
    int s = 0;
    g_off[0] = 0;
    for (int e = 0; e < En; e++) { s += g_cnt[e]; g_off[e + 1] = s; }
}

__global__ void k_place(const int* __restrict__ ids, const float* __restrict__ w) {
    int p = blockIdx.x * blockDim.x + threadIdx.x;
    if (p >= NP) return;
    int t = p >> 1, k = p & 1;
    bool valid = (k == 1) || (ids[2 * t] != ids[2 * t + 1]);
    if (!valid) return;
    int e = ids[p];
    int pos = g_off[e] + atomicAdd(&g_cur[e], 1);
    g_tok[pos] = t;
    g_w[pos]   = w[p];
}

// ---------------- GEMM1: act = silu(Xg @ wi_0[e]) * (Xg @ wi_1[e]) ---------
// Tile 64x64x16, 256 threads, 4x4 microtile per thread, two accumulators
// (gate + up) sharing one A tile.
__global__ __launch_bounds__(256) void k_gemm1(
    const float* __restrict__ X,
    const float* __restrict__ W0,
    const float* __restrict__ W1)
{
    __shared__ float As[BK][BM + 4];      // +4 keeps float4 alignment, kills conflicts
    __shared__ float B0s[BK][BN];
    __shared__ float B1s[BK][BN];
    __shared__ int   toks[BM];

    int e   = blockIdx.z;
    int beg = g_off[e];
    int ne  = g_off[e + 1] - beg;
    int r0  = blockIdx.y * BM;
    if (r0 >= ne) return;                 // uniform early-exit for empty tiles
    int n0  = blockIdx.x * BN;

    int tid = threadIdx.x;
    int tx  = tid & 15, ty = tid >> 4;

    if (tid < BM) {
        int r = r0 + tid;
        toks[tid] = (r < ne) ? g_tok[beg + r] : -1;
    }
    __syncthreads();

    const float* w0e = W0 + (size_t)e * Hn * Dn;
    const float* w1e = W1 + (size_t)e * Hn * Dn;

    // A-load mapping: each thread loads float4 along k of one gathered row
    int am = (tid * 4) >> 4;              // 0..63
    int ak = (tid * 4) & 15;              // 0,4,8,12
    int atok = toks[am];
    const float* aptr = (atok >= 0) ? (X + (size_t)atok * Hn + ak) : nullptr;
    // B-load mapping: float4 along n, coalesced
    int bn = (tid * 4) & 63;
    int bk = (tid * 4) >> 6;

    float acc0[4][4] = {}, acc1[4][4] = {};

    for (int k0 = 0; k0 < Hn; k0 += BK) {
        float4 av = make_float4(0.f, 0.f, 0.f, 0.f);
        if (aptr) av = *reinterpret_cast<const float4*>(aptr + k0);
        As[ak + 0][am] = av.x; As[ak + 1][am] = av.y;
        As[ak + 2][am] = av.z; As[ak + 3][am] = av.w;

        *reinterpret_cast<float4*>(&B0s[bk][bn]) =
            *reinterpret_cast<const float4*>(w0e + (size_t)(k0 + bk) * Dn + n0 + bn);
        *reinterpret_cast<float4*>(&B1s[bk][bn]) =
            *reinterpret_cast<const float4*>(w1e + (size_t)(k0 + bk) * Dn + n0 + bn);
        __syncthreads();

        #pragma unroll
        for (int kk = 0; kk < BK; kk++) {
            float4 a  = *reinterpret_cast<const float4*>(&As[kk][ty * 4]);
            float4 b0 = *reinterpret_cast<const float4*>(&B0s[kk][tx * 4]);
            float4 b1 = *reinterpret_cast<const float4*>(&B1s[kk][tx * 4]);
            float aa[4]  = {a.x, a.y, a.z, a.w};
            float bb0[4] = {b0.x, b0.y, b0.z, b0.w};
            float bb1[4] = {b1.x, b1.y, b1.z, b1.w};
            #pragma unroll
            for (int i = 0; i < 4; i++)
                #pragma unroll
                for (int j = 0; j < 4; j++) {
                    acc0[i][j] += aa[i] * bb0[j];
                    acc1[i][j] += aa[i] * bb1[j];
                }
        }
        __syncthreads();
    }

    #pragma unroll
    for (int i = 0; i < 4; i++) {
        int r = r0 + ty * 4 + i;
        if (r >= ne) continue;
        float4 o;
        float v[4];
        #pragma unroll
        for (int j = 0; j < 4; j++) {
            float g = acc0[i][j];
            float s = g / (1.f + __expf(-g));   // silu
            v[j] = s * acc1[i][j];
        }
        o.x = v[0]; o.y = v[1]; o.z = v[2]; o.w = v[3];
        *reinterpret_cast<float4*>(&g_act[(size_t)(beg + r) * Dn + n0 + tx * 4]) = o;
    }
}

// ---------------- GEMM2: out[tok] += w * (act @ wo[e]) ---------------------
__global__ __launch_bounds__(256) void k_gemm2(
    const float* __restrict__ WO,
    float* __restrict__ out)
{
    __shared__ float As[BK][BM + 4];
    __shared__ float Bs[BK][BN];
    __shared__ int   toks[BM];
    __shared__ float ws[BM];

    int e   = blockIdx.z;
    int beg = g_off[e];
    int ne  = g_off[e + 1] - beg;
    int r0  = blockIdx.y * BM;
    if (r0 >= ne) return;
    int n0  = blockIdx.x * BN;

    int tid = threadIdx.x;
    int tx  = tid & 15, ty = tid >> 4;

    if (tid < BM) {
        int r = r0 + tid;
        if (r < ne) { toks[tid] = g_tok[beg + r]; ws[tid] = g_w[beg + r]; }
        else        { toks[tid] = -1;             ws[tid] = 0.f; }
    }
    __syncthreads();

    const float* we = WO + (size_t)e * Dn * Hn;

    int am = (tid * 4) >> 4;
    int ak = (tid * 4) & 15;
    int arow = r0 + am;
    const float* aptr = (arow < ne) ? &g_act[(size_t)(beg + arow) * Dn + ak] : nullptr;
    int bn = (tid * 4) & 63;
    int bk = (tid * 4) >> 6;

    float acc[4][4] = {};

    for (int k0 = 0; k0 < Dn; k0 += BK) {
        float4 av = make_float4(0.f, 0.f, 0.f, 0.f);
        if (aptr) av = *reinterpret_cast<const float4*>(aptr + k0);
        As[ak + 0][am] = av.x; As[ak + 1][am] = av.y;
        As[ak + 2][am] = av.z; As[ak + 3][am] = av.w;

        *reinterpret_cast<float4*>(&Bs[bk][bn]) =
            *reinterpret_cast<const float4*>(we + (size_t)(k0 + bk) * Hn + n0 + bn);
        __syncthreads();

        #pragma unroll
        for (int kk = 0; kk < BK; kk++) {
            float4 a = *reinterpret_cast<const float4*>(&As[kk][ty * 4]);
            float4 b = *reinterpret_cast<const float4*>(&Bs[kk][tx * 4]);
            float aa[4] = {a.x, a.y, a.z, a.w};
            float bb[4] = {b.x, b.y, b.z, b.w};
            #pragma unroll
            for (int i = 0; i < 4; i++)
                #pragma unroll
                for (int j = 0; j < 4; j++)
                    acc[i][j] += aa[i] * bb[j];
        }
        __syncthreads();
    }

    #pragma unroll
    for (int i = 0; i < 4; i++) {
        int r = r0 + ty * 4 + i;
        if (r >= ne) continue;
        int   tok = toks[ty * 4 + i];
        float wgt = ws[ty * 4 + i];
        float* op = out + (size_t)tok * Hn + n0 + tx * 4;
        #pragma unroll
        for (int j = 0; j < 4; j++)
            atomicAdd(op + j, wgt * acc[i][j]);
    }
}

// ---------------- launch ----------------------------------------------------
extern "C" void kernel_launch(void* const* d_in, const int* in_sizes, int n_in,
                              void* d_out, int out_size) {
    const float* X  = (const float*)d_in[0];   // hidden_states [T,H]
    const float* tw = (const float*)d_in[1];   // topk_weights  [T,K]
    const int*   ti = (const int*)d_in[2];     // topk_ids      [T,K]
    const float* W0 = (const float*)d_in[3];   // wi_0 [E,H,D]
    const float* W1 = (const float*)d_in[4];   // wi_1 [E,H,D]
    const float* WO = (const float*)d_in[5];   // wo   [E,D,H]
    float* out = (float*)d_out;                // [T,H] f32

    k_reset<<<(Tn * Hn + 255) / 256, 256>>>(out);
    k_count<<<(NP + 255) / 256, 256>>>(ti);
    k_scan<<<1, 1>>>();
    k_place<<<(NP + 255) / 256, 256>>>(ti, tw);

    dim3 g1(Dn / BN, NP / BM, En);   // (32, 128, 8); empty row-tiles exit early
    k_gemm1<<<g1, 256>>>(X, W0, W1);

    dim3 g2(Hn / BN, NP / BM, En);   // (16, 128, 8)
    k_gemm2<<<g2, 256>>>(WO, out);
}